// round 17
// baseline (speedup 1.0000x reference)
#include <cuda_runtime.h>
#include <cuda_fp16.h>
#include <cstdint>
#include <math.h>

#define B_ 8
#define S_ 1024
#define D_ 1024
#define H_ 16
#define DK_ 64

// ---------------------------------------------------------------------------
// Scratch (device globals: allocation-free)
// ---------------------------------------------------------------------------
__device__ __align__(256) __half g_q[B_*H_*S_*DK_];
__device__ __align__(256) __half g_k[B_*H_*S_*DK_];
__device__ __align__(256) __half g_v[B_*H_*S_*DK_];
__device__ __align__(256) __half g_a1[8192*1024];     // activations; a1 reused for ctx
__device__ __align__(256) __half g_a2[8192*1024];
__device__ __align__(256) __half g_a3[8192*1024];
__device__ __align__(256) __half g_w1[1024*1024];
__device__ __align__(256) __half g_w2[1024*1024];
__device__ __align__(256) __half g_w3[1024*1024];
__device__ __align__(256) __half g_w4[1024*1024];
__device__ __align__(256) uint32_t g_pmask[B_*S_*(S_/32)];  // packed mask bits

// ---------------------------------------------------------------------------
// PTX helpers
// ---------------------------------------------------------------------------
__device__ __forceinline__ uint32_t smem_u32(const void* p) {
    uint32_t a;
    asm("{ .reg .u64 t; cvta.to.shared.u64 t, %1; cvt.u32.u64 %0, t; }" : "=r"(a) : "l"(p));
    return a;
}
__device__ __forceinline__ void cp_async16(uint32_t saddr, const void* gaddr) {
    asm volatile("cp.async.cg.shared.global [%0], [%1], 16;" :: "r"(saddr), "l"(gaddr));
}
__device__ __forceinline__ void cp_commit() {
    asm volatile("cp.async.commit_group;" ::: "memory");
}
template<int N>
__device__ __forceinline__ void cp_wait() {
    asm volatile("cp.async.wait_group %0;" :: "n"(N) : "memory");
}
__device__ __forceinline__ void ldsm_x4(uint32_t* r, uint32_t addr) {
    asm volatile("ldmatrix.sync.aligned.m8n8.x4.shared.b16 {%0,%1,%2,%3}, [%4];"
                 : "=r"(r[0]), "=r"(r[1]), "=r"(r[2]), "=r"(r[3]) : "r"(addr));
}
__device__ __forceinline__ void ldsm_x4_t(uint32_t* r, uint32_t addr) {
    asm volatile("ldmatrix.sync.aligned.m8n8.x4.trans.shared.b16 {%0,%1,%2,%3}, [%4];"
                 : "=r"(r[0]), "=r"(r[1]), "=r"(r[2]), "=r"(r[3]) : "r"(addr));
}
__device__ __forceinline__ void mma_fp16(float* d, const uint32_t* a, const uint32_t* b) {
    asm volatile(
        "mma.sync.aligned.m16n8k16.row.col.f32.f16.f16.f32 "
        "{%0,%1,%2,%3}, {%4,%5,%6,%7}, {%8,%9}, {%0,%1,%2,%3};"
        : "+f"(d[0]), "+f"(d[1]), "+f"(d[2]), "+f"(d[3])
        : "r"(a[0]), "r"(a[1]), "r"(a[2]), "r"(a[3]), "r"(b[0]), "r"(b[1]));
}
__device__ __forceinline__ float fexp2(float x) {
    float r; asm("ex2.approx.f32 %0, %1;" : "=f"(r) : "f"(x)); return r;
}
__device__ __forceinline__ uint32_t packh2(float x, float y) {
    __half2 t = __floats2half2_rn(x, y);
    return *(uint32_t*)&t;
}

// ---------------------------------------------------------------------------
// Conversions (batched over grid.y)
// ---------------------------------------------------------------------------
__device__ __forceinline__ void conv8(const float* src, __half* dst, size_t g) {
    const float4 a0 = *(const float4*)(src + g);
    const float4 a1 = *(const float4*)(src + g + 4);
    __align__(16) __half hv[8];
    hv[0] = __float2half_rn(a0.x); hv[1] = __float2half_rn(a0.y);
    hv[2] = __float2half_rn(a0.z); hv[3] = __float2half_rn(a0.w);
    hv[4] = __float2half_rn(a1.x); hv[5] = __float2half_rn(a1.y);
    hv[6] = __float2half_rn(a1.z); hv[7] = __float2half_rn(a1.w);
    *(uint4*)(dst + g) = *(const uint4*)hv;
}

__global__ __launch_bounds__(256) void conv_a3_kernel(
    const float* __restrict__ s0, const float* __restrict__ s1,
    const float* __restrict__ s2,
    __half* __restrict__ d0, __half* __restrict__ d1, __half* __restrict__ d2)
{
    const size_t g = ((size_t)blockIdx.x * 256 + threadIdx.x) * 8;
    const int z = blockIdx.y;
    const float* s = (z == 0) ? s0 : (z == 1) ? s1 : s2;
    __half* d = (z == 0) ? d0 : (z == 1) ? d1 : d2;
    conv8(s, d, g);
}

__global__ __launch_bounds__(256) void conv_w4_kernel(
    const float* __restrict__ s0, const float* __restrict__ s1,
    const float* __restrict__ s2, const float* __restrict__ s3,
    __half* __restrict__ d0, __half* __restrict__ d1,
    __half* __restrict__ d2, __half* __restrict__ d3)
{
    const size_t g = ((size_t)blockIdx.x * 256 + threadIdx.x) * 8;
    const int z = blockIdx.y;
    const float* s = (z == 0) ? s0 : (z == 1) ? s1 : (z == 2) ? s2 : s3;
    __half* d = (z == 0) ? d0 : (z == 1) ? d1 : (z == 2) ? d2 : d3;
    conv8(s, d, g);
}

// Pack mask: [B,S,S] int32 -> [B,S,S/32] uint32 bits.
__global__ __launch_bounds__(256) void mask_pack_kernel(
    const int* __restrict__ mask, uint32_t* __restrict__ pm)
{
    const size_t w = (size_t)blockIdx.x * 256 + threadIdx.x;
    const int* src = mask + w * 32;
    uint32_t bits = 0;
    #pragma unroll
    for (int i = 0; i < 8; i++) {
        const int4 v = *(const int4*)(src + i * 4);
        bits |= (v.x ? 1u : 0u) << (i * 4 + 0);
        bits |= (v.y ? 1u : 0u) << (i * 4 + 1);
        bits |= (v.z ? 1u : 0u) << (i * 4 + 2);
        bits |= (v.w ? 1u : 0u) << (i * 4 + 3);
    }
    pm[w] = bits;
}

// ---------------------------------------------------------------------------
// fp16 GEMM core — BK=64 per stage (half the barriers of BK=32),
// 144B row stride (ldsm conflict-free), 3 stages, 2 CTAs/SM.
// ---------------------------------------------------------------------------
static constexpr int G_RS = 144;                    // bytes per smem row
static constexpr int G_TILE = 128 * G_RS;           // 18432
static constexpr int OFF_A = 0;
static constexpr int OFF_B = G_TILE;
static constexpr int G_STAGE = 2 * G_TILE;          // 36864
static constexpr int SMEM_GEMM = 3 * G_STAGE;       // 110592

struct GemmAcc { float a[4][4][4]; };

__device__ __forceinline__ void gemm_core(
    uint32_t sb, int tid, const __half* A_, const __half* B_v,
    int m0, int n0, GemmAcc& acc_)
{
    const int wid = tid >> 5, lane = tid & 31;
    const int warp_m = wid >> 2;
    const int warp_n = wid & 3;

    // loader: thread t -> row t>>1, chunks (t&1)*4..+3 of both tiles
    const int lrow = tid >> 1;
    const int lcb = (tid & 1) * 4;

    auto issue_stage = [&](int kt, int stg) {
        const uint32_t s0 = sb + stg * G_STAGE;
        const int kbase = kt * 64;
        #pragma unroll
        for (int c = 0; c < 4; c++) {
            const int ch = lcb + c;                      // 0..7
            const uint32_t so = (uint32_t)lrow * G_RS + ch * 16;
            const int k0 = kbase + ch * 8;
            cp_async16(s0 + OFF_A + so, A_  + (size_t)(m0 + lrow) * 1024 + k0);
            cp_async16(s0 + OFF_B + so, B_v + (size_t)(n0 + lrow) * 1024 + k0);
        }
        cp_commit();
    };

    float (&acc)[4][4][4] = acc_.a;
    #pragma unroll
    for (int mi = 0; mi < 4; mi++)
        #pragma unroll
        for (int ni = 0; ni < 4; ni++)
            #pragma unroll
            for (int e = 0; e < 4; e++) acc[mi][ni][e] = 0.f;

    issue_stage(0, 0);
    issue_stage(1, 1);

    const int la = lane & 15;
    const int lah = (lane >> 4) * 16;
    const int lbrow = ((lane >> 4) * 8) + (lane & 7);
    const int lboff = ((lane >> 3) & 1) * 16;

    int stg = 0;
    for (int kt = 0; kt < 16; kt++) {     // 16 iterations of BK=64
        cp_wait<1>();
        __syncthreads();
        if (kt + 2 < 16) {
            int ns = stg + 2; if (ns >= 3) ns -= 3;
            issue_stage(kt + 2, ns);
        } else {
            cp_commit();
        }

        const uint32_t s0 = sb + stg * G_STAGE;
        #pragma unroll
        for (int kk = 0; kk < 4; kk++) {   // 4 k16-chunks
            uint32_t ah[4][4], bf[2][4];
            #pragma unroll
            for (int mi = 0; mi < 4; mi++) {
                const uint32_t ro =
                    (uint32_t)(warp_m * 64 + mi * 16 + la) * G_RS + lah + kk * 32;
                ldsm_x4(ah[mi], s0 + OFF_A + ro);
            }
            #pragma unroll
            for (int nb = 0; nb < 2; nb++) {
                const uint32_t ro =
                    (uint32_t)(warp_n * 32 + nb * 16 + lbrow) * G_RS + lboff + kk * 32;
                ldsm_x4(bf[nb], s0 + OFF_B + ro);
            }
            #pragma unroll
            for (int mi = 0; mi < 4; mi++)
                #pragma unroll
                for (int nb = 0; nb < 2; nb++) {
                    mma_fp16(acc[mi][2 * nb],     ah[mi], bf[nb]);
                    mma_fp16(acc[mi][2 * nb + 1], ah[mi], bf[nb] + 2);
                }
        }
        if (++stg == 3) stg = 0;
    }
    __syncthreads();
}

// Batched QKV projection: grid (8, 64, 3)
__global__ __launch_bounds__(256, 2) void gemm_qkv_kernel(
    const __half* __restrict__ A0, const __half* __restrict__ A1,
    const __half* __restrict__ A2,
    const __half* __restrict__ W0, const __half* __restrict__ W1,
    const __half* __restrict__ W2,
    const float* __restrict__ b0, const float* __restrict__ b1,
    const float* __restrict__ b2,
    float qscale,
    __half* __restrict__ Y0, __half* __restrict__ Y1, __half* __restrict__ Y2)
{
    extern __shared__ char smem[];
    const uint32_t sb = smem_u32(smem);
    const int tid = threadIdx.x;
    const int z = blockIdx.z;
    const __half* A_ = (z == 0) ? A0 : (z == 1) ? A1 : A2;
    const __half* W_ = (z == 0) ? W0 : (z == 1) ? W1 : W2;
    const float* bias = (z == 0) ? b0 : (z == 1) ? b1 : b2;
    __half* Yh = (z == 0) ? Y0 : (z == 1) ? Y1 : Y2;
    const float scale = (z == 0) ? qscale : 1.0f;

    const int m0 = blockIdx.y * 128;
    const int n0 = blockIdx.x * 128;

    GemmAcc acc;
    gemm_core(sb, tid, A_, W_, m0, n0, acc);

    const int wid = tid >> 5, lane = tid & 31;
    const int warp_m = wid >> 2, warp_n = wid & 3;
    const int lr = lane >> 2;
    const int lc = (lane & 3) * 2;
    #pragma unroll
    for (int mi = 0; mi < 4; mi++) {
        #pragma unroll
        for (int ni = 0; ni < 4; ni++) {
            const int n = n0 + warp_n * 32 + ni * 8 + lc;
            const float bx = __ldg(bias + n);
            const float by = __ldg(bias + n + 1);
            const int r0 = m0 + warp_m * 64 + mi * 16 + lr;
            const int r1 = r0 + 8;
            const float v00 = (acc.a[mi][ni][0] + bx) * scale;
            const float v01 = (acc.a[mi][ni][1] + by) * scale;
            const float v10 = (acc.a[mi][ni][2] + bx) * scale;
            const float v11 = (acc.a[mi][ni][3] + by) * scale;
            const int h_ = n >> 6, dk = n & 63;
            const size_t a0 = (((size_t)((r0 >> 10) * H_ + h_)) * S_ + (r0 & 1023)) * DK_ + dk;
            const size_t a1 = (((size_t)((r1 >> 10) * H_ + h_)) * S_ + (r1 & 1023)) * DK_ + dk;
            *(uint32_t*)(Yh + a0) = packh2(v00, v01);
            *(uint32_t*)(Yh + a1) = packh2(v10, v11);
        }
    }
}

// O projection: fp32 out
__global__ __launch_bounds__(256, 2) void gemm_o_kernel(
    const __half* __restrict__ A_, const __half* __restrict__ W_,
    const float* __restrict__ bias, float* __restrict__ Yf)
{
    extern __shared__ char smem[];
    const uint32_t sb = smem_u32(smem);
    const int tid = threadIdx.x;
    const int m0 = blockIdx.y * 128;
    const int n0 = blockIdx.x * 128;

    GemmAcc acc;
    gemm_core(sb, tid, A_, W_, m0, n0, acc);

    const int wid = tid >> 5, lane = tid & 31;
    const int warp_m = wid >> 2, warp_n = wid & 3;
    const int lr = lane >> 2;
    const int lc = (lane & 3) * 2;
    #pragma unroll
    for (int mi = 0; mi < 4; mi++) {
        #pragma unroll
        for (int ni = 0; ni < 4; ni++) {
            const int n = n0 + warp_n * 32 + ni * 8 + lc;
            const float bx = __ldg(bias + n);
            const float by = __ldg(bias + n + 1);
            const int r0 = m0 + warp_m * 64 + mi * 16 + lr;
            const int r1 = r0 + 8;
            *(float2*)(Yf + (size_t)r0 * D_ + n) =
                make_float2(acc.a[mi][ni][0] + bx, acc.a[mi][ni][1] + by);
            *(float2*)(Yf + (size_t)r1 * D_ + n) =
                make_float2(acc.a[mi][ni][2] + bx, acc.a[mi][ni][3] + by);
        }
    }
}

// ---------------------------------------------------------------------------
// Flash attention, all-fp16, bit-packed mask (unchanged from R16).
// ---------------------------------------------------------------------------
static constexpr int FRS = 144;
static constexpr int F_OFF_Q  = 0;
static constexpr int F_OFF_KV = 128 * FRS;
static constexpr int F_TILE   = 64 * FRS;
static constexpr int F_STAGE  = 2 * F_TILE;
static constexpr int SMEM_FLASH = F_OFF_KV + 2 * F_STAGE;  // 55296

__global__ __launch_bounds__(256, 2) void flash_mma_kernel(
    const __half* __restrict__ Qf_,
    const __half* __restrict__ Kf_, const __half* __restrict__ Vf_,
    const uint32_t* __restrict__ pmask,
    __half* __restrict__ Ctx_)
{
    extern __shared__ char smem[];
    const uint32_t sb = smem_u32(smem);
    const int tid = threadIdx.x, w = tid >> 5, lane = tid & 31;
    const int bh = blockIdx.y, b = bh >> 4, h = bh & 15;
    const int q0 = blockIdx.x * 128;

    const size_t hoff = (size_t)bh * S_ * DK_;
    const __half* Qf = Qf_ + hoff;
    const __half* Kf = Kf_ + hoff;
    const __half* Vf = Vf_ + hoff;

    auto load_kv = [&](int kb, int stg) {
        const uint32_t s0 = sb + F_OFF_KV + stg * F_STAGE;
        const int row = tid >> 2;
        const int cp0 = (tid & 3) * 2;
        const size_t gro = (size_t)(kb * 64 + row) * DK_;
        #pragma unroll
        for (int c = 0; c < 2; c++) {
            const uint32_t so = (uint32_t)row * FRS + (cp0 + c) * 16;
            const size_t go = gro + (cp0 + c) * 8;
            cp_async16(s0 + 0 * F_TILE + so, Kf + go);
            cp_async16(s0 + 1 * F_TILE + so, Vf + go);
        }
        cp_commit();
    };

    {
        const int row = tid >> 1;
        const int cp0 = (tid & 1) * 4;
        const size_t g = (size_t)(q0 + row) * DK_;
        #pragma unroll
        for (int c = 0; c < 4; c++) {
            const uint32_t so = (uint32_t)row * FRS + (cp0 + c) * 16;
            cp_async16(sb + F_OFF_Q + so, Qf + g + (cp0 + c) * 8);
        }
    }
    cp_commit();
    load_kv(0, 0);
    cp_wait<0>();
    __syncthreads();

    uint32_t qf[4][4];
    {
        const int la = lane & 15;
        const int half = (lane >> 4) * 16;
        #pragma unroll
        for (int c = 0; c < 4; c++) {
            const uint32_t ro = (uint32_t)(w * 16 + la) * FRS + half + c * 32;
            ldsm_x4(qf[c], sb + F_OFF_Q + ro);
        }
    }

    float Of[8][4];
    #pragma unroll
    for (int j = 0; j < 8; j++)
        #pragma unroll
        for (int e = 0; e < 4; e++) Of[j][e] = 0.f;
    float m0 = -1e30f, m1 = -1e30f, l0 = 0.f, l1 = 0.f;

    const int lr = lane >> 2, lq = lane & 3;
    const int qrow0 = q0 + w * 16 + lr;
    const uint32_t* pm0 = pmask + ((size_t)b * S_ + qrow0) * (S_ / 32);
    const uint32_t* pm1 = pm0 + 8 * (S_ / 32);

    const int lm = lane >> 3, lr8 = lane & 7;
    const uint32_t kbase = (uint32_t)(((lm >> 1) * 8 + lr8)) * FRS + (lm & 1) * 16;
    const uint32_t vbase = (uint32_t)(((lm & 1) * 8 + lr8)) * FRS + (lm >> 1) * 16;

    for (int kb = 0; kb < 16; kb++) {
        if (kb > 0) { cp_wait<0>(); __syncthreads(); }
        if (kb + 1 < 16) load_kv(kb + 1, (kb + 1) & 1);

        const uint32_t kvb = sb + F_OFF_KV + (kb & 1) * F_STAGE;

        float Sf[8][4];
        #pragma unroll
        for (int j = 0; j < 8; j++)
            #pragma unroll
            for (int e = 0; e < 4; e++) Sf[j][e] = 0.f;

        #pragma unroll
        for (int c = 0; c < 4; c++) {
            #pragma unroll
            for (int pr = 0; pr < 4; pr++) {
                uint32_t kh[4];
                const uint32_t a = kvb + (uint32_t)pr * 16 * FRS + c * 32 + kbase;
                ldsm_x4(kh, a);
                mma_fp16(Sf[2 * pr],     qf[c], kh);
                mma_fp16(Sf[2 * pr + 1], qf[c], kh + 2);
            }
        }

        {
            const uint2 mA = *(const uint2*)(pm0 + kb * 2);
            const uint2 mB = *(const uint2*)(pm1 + kb * 2);
            if ((mA.x & mA.y & mB.x & mB.y) != 0xFFFFFFFFu) {
                #pragma unroll
                for (int j = 0; j < 8; j++) {
                    const int bit = (j & 3) * 8 + lq * 2;
                    const uint32_t wa = (j < 4) ? mA.x : mA.y;
                    const uint32_t wb = (j < 4) ? mB.x : mB.y;
                    if (!((wa >> bit) & 1u))       Sf[j][0] = -1e30f;
                    if (!((wa >> (bit + 1)) & 1u)) Sf[j][1] = -1e30f;
                    if (!((wb >> bit) & 1u))       Sf[j][2] = -1e30f;
                    if (!((wb >> (bit + 1)) & 1u)) Sf[j][3] = -1e30f;
                }
            }
        }

        float rm0 = Sf[0][0], rm1 = Sf[0][2];
        #pragma unroll
        for (int j = 0; j < 8; j++) {
            rm0 = fmaxf(rm0, fmaxf(Sf[j][0], Sf[j][1]));
            rm1 = fmaxf(rm1, fmaxf(Sf[j][2], Sf[j][3]));
        }
        rm0 = fmaxf(rm0, __shfl_xor_sync(0xffffffffu, rm0, 1));
        rm0 = fmaxf(rm0, __shfl_xor_sync(0xffffffffu, rm0, 2));
        rm1 = fmaxf(rm1, __shfl_xor_sync(0xffffffffu, rm1, 1));
        rm1 = fmaxf(rm1, __shfl_xor_sync(0xffffffffu, rm1, 2));
        const float mn0 = fmaxf(m0, rm0);
        const float mn1 = fmaxf(m1, rm1);
        const float cr0 = fexp2(m0 - mn0);
        const float cr1 = fexp2(m1 - mn1);
        m0 = mn0; m1 = mn1;

        float s0 = 0.f, s1 = 0.f;
        #pragma unroll
        for (int j = 0; j < 8; j++) {
            Sf[j][0] = fexp2(Sf[j][0] - mn0);
            Sf[j][1] = fexp2(Sf[j][1] - mn0);
            Sf[j][2] = fexp2(Sf[j][2] - mn1);
            Sf[j][3] = fexp2(Sf[j][3] - mn1);
            s0 += Sf[j][0] + Sf[j][1];
            s1 += Sf[j][2] + Sf[j][3];
        }
        s0 += __shfl_xor_sync(0xffffffffu, s0, 1);
        s0 += __shfl_xor_sync(0xffffffffu, s0, 2);
        s1 += __shfl_xor_sync(0xffffffffu, s1, 1);
        s1 += __shfl_xor_sync(0xffffffffu, s1, 2);
        l0 = l0 * cr0 + s0;
        l1 = l1 * cr1 + s1;

        #pragma unroll
        for (int j = 0; j < 8; j++) {
            Of[j][0] *= cr0; Of[j][1] *= cr0;
            Of[j][2] *= cr1; Of[j][3] *= cr1;
        }

        #pragma unroll
        for (int c = 0; c < 4; c++) {
            uint32_t ph[4];
            ph[0] = packh2(Sf[2 * c][0],     Sf[2 * c][1]);
            ph[1] = packh2(Sf[2 * c][2],     Sf[2 * c][3]);
            ph[2] = packh2(Sf[2 * c + 1][0], Sf[2 * c + 1][1]);
            ph[3] = packh2(Sf[2 * c + 1][2], Sf[2 * c + 1][3]);
            #pragma unroll
            for (int dp = 0; dp < 4; dp++) {
                uint32_t vh[4];
                const uint32_t a = kvb + F_TILE + (uint32_t)c * 16 * FRS + dp * 32 + vbase;
                ldsm_x4_t(vh, a);
                mma_fp16(Of[2 * dp],     ph, vh);
                mma_fp16(Of[2 * dp + 1], ph, vh + 2);
            }
        }
    }

    const float inv0 = 1.f / l0;
    const float inv1 = 1.f / l1;
    const size_t row0 = (size_t)(b * S_ + qrow0) * D_;
    const size_t row1 = row0 + 8 * D_;
    #pragma unroll
    for (int j = 0; j < 8; j++) {
        const int col = h * 64 + j * 8 + lq * 2;
        *(uint32_t*)(Ctx_ + row0 + col) = packh2(Of[j][0] * inv0, Of[j][1] * inv0);
        *(uint32_t*)(Ctx_ + row1 + col) = packh2(Of[j][2] * inv1, Of[j][3] * inv1);
    }
}

// ---------------------------------------------------------------------------
extern "C" void kernel_launch(void* const* d_in, const int* in_sizes, int n_in,
                              void* d_out, int out_size) {
    const float* query = (const float*)d_in[0];
    const float* key   = (const float*)d_in[1];
    const float* value = (const float*)d_in[2];
    const int*   mask  = (const int*)d_in[3];
    const float* wq = (const float*)d_in[4];
    const float* bq = (const float*)d_in[5];
    const float* wk = (const float*)d_in[6];
    const float* bk = (const float*)d_in[7];
    const float* wv = (const float*)d_in[8];
    const float* bv = (const float*)d_in[9];
    const float* wo = (const float*)d_in[10];
    const float* bo = (const float*)d_in[11];
    float* out = (float*)d_out;

    __half *qf, *kf, *vf, *a1, *a2, *a3, *w1, *w2, *w3, *w4;
    uint32_t* pm;
    cudaGetSymbolAddress((void**)&qf, g_q);
    cudaGetSymbolAddress((void**)&kf, g_k);
    cudaGetSymbolAddress((void**)&vf, g_v);
    cudaGetSymbolAddress((void**)&a1, g_a1);
    cudaGetSymbolAddress((void**)&a2, g_a2);
    cudaGetSymbolAddress((void**)&a3, g_a3);
    cudaGetSymbolAddress((void**)&w1, g_w1);
    cudaGetSymbolAddress((void**)&w2, g_w2);
    cudaGetSymbolAddress((void**)&w3, g_w3);
    cudaGetSymbolAddress((void**)&w4, g_w4);
    cudaGetSymbolAddress((void**)&pm, g_pmask);

    cudaFuncSetAttribute(gemm_qkv_kernel,
                         cudaFuncAttributeMaxDynamicSharedMemorySize, SMEM_GEMM);
    cudaFuncSetAttribute(gemm_o_kernel,
                         cudaFuncAttributeMaxDynamicSharedMemorySize, SMEM_GEMM);
    cudaFuncSetAttribute(flash_mma_kernel,
                         cudaFuncAttributeMaxDynamicSharedMemorySize, SMEM_FLASH);

    const int convA = (8192 * 1024 / 8) / 256;   // 4096
    const int convW = (1024 * 1024 / 8) / 256;   // 512
    const int packG = (B_ * S_ * (S_ / 32)) / 256;  // 1024
    const float qscale = 0.125f * 1.4426950408889634f;  // 1/sqrt(64) * log2(e)

    conv_a3_kernel<<<dim3(convA, 3), 256>>>(query, key, value, a1, a2, a3);   // 1
    conv_w4_kernel<<<dim3(convW, 4), 256>>>(wq, wk, wv, wo, w1, w2, w3, w4);  // 2
    mask_pack_kernel<<<packG, 256>>>(mask, pm);                               // 3
    gemm_qkv_kernel<<<dim3(D_ / 128, (B_ * S_) / 128, 3), 256, SMEM_GEMM>>>(  // 4 <- profiled
        a1, a2, a3, w1, w2, w3, bq, bk, bv, qscale, qf, kf, vf);
    flash_mma_kernel<<<dim3(S_ / 128, B_ * H_), 256, SMEM_FLASH>>>(           // 5
        qf, kf, vf, pm, a1);
    gemm_o_kernel<<<dim3(D_ / 128, (B_ * S_) / 128), 256, SMEM_GEMM>>>(       // 6
        a1, w4, bo, out);
}